// round 2
// baseline (speedup 1.0000x reference)
#include <cuda_runtime.h>
#include <cuda_bf16.h>
#include <math.h>
#include <stdint.h>

// MultiResolutionHashGrid: N=1e6 points, L=16 levels, T=2^19 entries, F=2 feats.
// Round 2: (a) exploit hash structure — x hashes with prime 1, so when floor-x
// is even the two x-corners are adjacent table entries -> one float4 load;
// (b) stage per-thread output in smem, flush warp-coalesced as STG.128.

#define L_LEVELS 16
#define T_SIZE   524288u          // 2^19
#define T_MASK   (T_SIZE - 1u)
#define P1 2654435761u
#define P2 805459861u

struct ResArr { float r[L_LEVELS]; };

__global__ __launch_bounds__(256)
void hashgrid_kernel(const float* __restrict__ pos,
                     const float* __restrict__ table,
                     float4* __restrict__ out4,
                     int N, ResArr res)
{
    // 256 threads x 9 float4 (8 data + 1 pad to kill bank conflicts) = 36 KB
    __shared__ float4 sm[256][9];

    const int t    = threadIdx.x;
    const int lane = t & 31;
    const int wrow = t & ~31;                       // warp's first row in sm
    const int n    = blockIdx.x * blockDim.x + t;
    const bool active = (n < N);

    if (active) {
        const float HI = 1.0f - 1e-6f;
        float px = pos[3 * n + 0];
        float py = pos[3 * n + 1];
        float pz = pos[3 * n + 2];
        // normalized = clip((p + 1) / 2.0, 0, 1-1e-6)   (2+1e-8 == 2.0f in f32)
        float nx = fminf(fmaxf((px + 1.0f) * 0.5f, 0.0f), HI);
        float ny = fminf(fmaxf((py + 1.0f) * 0.5f, 0.0f), HI);
        float nz = fminf(fmaxf((pz + 1.0f) * 0.5f, 0.0f), HI);

        const float2* tbl2 = reinterpret_cast<const float2*>(table);
        float2* mysm = reinterpret_cast<float2*>(&sm[t][0]);

        #pragma unroll
        for (int l = 0; l < L_LEVELS; ++l) {
            float rr = res.r[l];
            float sx = nx * rr, sy = ny * rr, sz = nz * rr;
            float fx0 = floorf(sx), fy0 = floorf(sy), fz0 = floorf(sz);
            float fx = sx - fx0, fy = sy - fy0, fz = sz - fz0;

            uint32_t cx = (uint32_t)(int32_t)fx0;
            uint32_t cy = (uint32_t)(int32_t)fy0;
            uint32_t cz = (uint32_t)(int32_t)fz0;

            uint32_t x0 = cx;            // prime 1
            uint32_t x1 = cx + 1u;
            uint32_t y0 = cy * P1;
            uint32_t y1 = y0 + P1;
            uint32_t z0 = cz * P2;
            uint32_t z1 = z0 + P2;

            const float2* tl = tbl2 + (size_t)l * T_SIZE;
            const float4* tl4 = reinterpret_cast<const float4*>(tl);
            const bool evenx = (cx & 1u) == 0u;

            // a = corner at x0, b = corner at x1, for mixed hash m = yh ^ zh
            float2 f000, f100, f001, f101, f010, f110, f011, f111;

            #define LOAD_PAIR(m, a, b)                                         \
            do {                                                               \
                uint32_t i0 = (x0 ^ (m)) & T_MASK;                             \
                if (evenx) {                                                   \
                    /* x1 = x0+1, x0 even -> i1 = i0 ^ 1: same float4 */       \
                    float4 v = __ldg(&tl4[i0 >> 1]);                           \
                    if (i0 & 1u) { (a) = make_float2(v.z, v.w);                \
                                   (b) = make_float2(v.x, v.y); }              \
                    else         { (a) = make_float2(v.x, v.y);                \
                                   (b) = make_float2(v.z, v.w); }              \
                } else {                                                       \
                    uint32_t i1 = (x1 ^ (m)) & T_MASK;                         \
                    (a) = __ldg(&tl[i0]);                                      \
                    (b) = __ldg(&tl[i1]);                                      \
                }                                                              \
            } while (0)

            LOAD_PAIR(y0 ^ z0, f000, f100);
            LOAD_PAIR(y0 ^ z1, f001, f101);
            LOAD_PAIR(y1 ^ z0, f010, f110);
            LOAD_PAIR(y1 ^ z1, f011, f111);
            #undef LOAD_PAIR

            float omz = 1.0f - fz;
            float c00x = f000.x * omz + f001.x * fz;
            float c00y = f000.y * omz + f001.y * fz;
            float c01x = f010.x * omz + f011.x * fz;
            float c01y = f010.y * omz + f011.y * fz;
            float c10x = f100.x * omz + f101.x * fz;
            float c10y = f100.y * omz + f101.y * fz;
            float c11x = f110.x * omz + f111.x * fz;
            float c11y = f110.y * omz + f111.y * fz;

            float omy = 1.0f - fy;
            float c0x = c00x * omy + c01x * fy;
            float c0y = c00y * omy + c01y * fy;
            float c1x = c10x * omy + c11x * fy;
            float c1y = c10y * omy + c11y * fy;

            float omx = 1.0f - fx;
            float2 o;
            o.x = c0x * omx + c1x * fx;
            o.y = c0y * omx + c1y * fx;
            mysm[l] = o;
        }
    }
    __syncwarp();

    // Coalesced flush: this warp owns points [warpBase, warpBase+32), i.e.
    // out4 indices [warpBase*8, warpBase*8+256). 8 fully-coalesced STG.128.
    const int warpBase = blockIdx.x * blockDim.x + wrow;
    float4* dst = out4 + (size_t)warpBase * 8;
    #pragma unroll
    for (int j = 0; j < 8; ++j) {
        int idx = j * 32 + lane;
        int p = idx >> 3;            // point within warp
        int k = idx & 7;             // float4 index within point
        if (warpBase + p < N)
            dst[idx] = sm[wrow + p][k];
    }
}

extern "C" void kernel_launch(void* const* d_in, const int* in_sizes, int n_in,
                              void* d_out, int out_size)
{
    const float* positions   = (const float*)d_in[0];   // (N, 3)
    const float* hash_tables = (const float*)d_in[1];   // (L, T, F)
    float4* out = (float4*)d_out;                       // (N, L*F) = (N,32) floats

    int N = in_sizes[0] / 3;

    // Same double-precision libm sequence as the Python reference:
    // GROWTH = exp((log(2048)-log(16))/15); res_l = ceil(16*GROWTH**l).
    ResArr res;
    double growth = exp((log(2048.0) - log(16.0)) / 15.0);
    for (int l = 0; l < L_LEVELS; ++l) {
        res.r[l] = (float)ceil(16.0 * pow(growth, (double)l));
    }

    int threads = 256;
    int blocks = (N + threads - 1) / threads;
    hashgrid_kernel<<<blocks, threads>>>(positions, hash_tables, out, N, res);
}

// round 3
// speedup vs baseline: 1.6385x; 1.6385x over previous
#include <cuda_runtime.h>
#include <cuda_bf16.h>
#include <math.h>
#include <stdint.h>

// MultiResolutionHashGrid: N=1e6, L=16, T=2^19, F=2.
// R3: R1's straight-line gather body (no branches in load path) +
// smem-staged warp-coalesced output stores (8x STG.128 per warp).

#define L_LEVELS 16
#define T_SIZE   524288u          // 2^19
#define T_MASK   (T_SIZE - 1u)
#define P1 2654435761u
#define P2 805459861u

struct ResArr { float r[L_LEVELS]; };

__global__ __launch_bounds__(256)
void hashgrid_kernel(const float* __restrict__ pos,
                     const float* __restrict__ table,
                     float4* __restrict__ out4,
                     int N, ResArr res)
{
    // 256 threads x (8 data + 1 pad) float4 = 36 KB. Pad keeps the
    // LDS.128 flush conflict-free (row stride 36 floats).
    __shared__ float4 sm[256][9];

    const int t    = threadIdx.x;
    const int lane = t & 31;
    const int wrow = t & ~31;
    const int n    = blockIdx.x * blockDim.x + t;

    if (n < N) {
        const float HI = 1.0f - 1e-6f;
        float px = pos[3 * n + 0];
        float py = pos[3 * n + 1];
        float pz = pos[3 * n + 2];
        // normalized = clip((p + 1) / 2.0, 0, 1-1e-6)   (2+1e-8 == 2.0f in f32)
        float nx = fminf(fmaxf((px + 1.0f) * 0.5f, 0.0f), HI);
        float ny = fminf(fmaxf((py + 1.0f) * 0.5f, 0.0f), HI);
        float nz = fminf(fmaxf((pz + 1.0f) * 0.5f, 0.0f), HI);

        const float2* tbl2 = reinterpret_cast<const float2*>(table);
        float2* mysm = reinterpret_cast<float2*>(&sm[t][0]);

        #pragma unroll
        for (int l = 0; l < L_LEVELS; ++l) {
            float rr = res.r[l];
            float sx = nx * rr, sy = ny * rr, sz = nz * rr;
            float fx0 = floorf(sx), fy0 = floorf(sy), fz0 = floorf(sz);
            float fx = sx - fx0, fy = sy - fy0, fz = sz - fz0;

            uint32_t cx = (uint32_t)(int32_t)fx0;
            uint32_t cy = (uint32_t)(int32_t)fy0;
            uint32_t cz = (uint32_t)(int32_t)fz0;

            uint32_t x0 = cx;            // prime 1
            uint32_t x1 = cx + 1u;
            uint32_t y0 = cy * P1;
            uint32_t y1 = y0 + P1;
            uint32_t z0 = cz * P2;
            uint32_t z1 = z0 + P2;

            const float2* tl = tbl2 + (size_t)l * T_SIZE;
            // corner order matches reference offsets:
            // [0,0,0],[0,0,1],[0,1,0],[0,1,1],[1,0,0],[1,0,1],[1,1,0],[1,1,1]
            float2 f000 = __ldg(&tl[(x0 ^ y0 ^ z0) & T_MASK]);
            float2 f001 = __ldg(&tl[(x0 ^ y0 ^ z1) & T_MASK]);
            float2 f010 = __ldg(&tl[(x0 ^ y1 ^ z0) & T_MASK]);
            float2 f011 = __ldg(&tl[(x0 ^ y1 ^ z1) & T_MASK]);
            float2 f100 = __ldg(&tl[(x1 ^ y0 ^ z0) & T_MASK]);
            float2 f101 = __ldg(&tl[(x1 ^ y0 ^ z1) & T_MASK]);
            float2 f110 = __ldg(&tl[(x1 ^ y1 ^ z0) & T_MASK]);
            float2 f111 = __ldg(&tl[(x1 ^ y1 ^ z1) & T_MASK]);

            float omz = 1.0f - fz;
            float c00x = f000.x * omz + f001.x * fz;
            float c00y = f000.y * omz + f001.y * fz;
            float c01x = f010.x * omz + f011.x * fz;
            float c01y = f010.y * omz + f011.y * fz;
            float c10x = f100.x * omz + f101.x * fz;
            float c10y = f100.y * omz + f101.y * fz;
            float c11x = f110.x * omz + f111.x * fz;
            float c11y = f110.y * omz + f111.y * fz;

            float omy = 1.0f - fy;
            float c0x = c00x * omy + c01x * fy;
            float c0y = c00y * omy + c01y * fy;
            float c1x = c10x * omy + c11x * fy;
            float c1y = c10y * omy + c11y * fy;

            float omx = 1.0f - fx;
            float2 o;
            o.x = c0x * omx + c1x * fx;
            o.y = c0y * omx + c1y * fx;
            mysm[l] = o;
        }
    }
    __syncwarp();

    // Coalesced flush: warp owns points [warpBase, warpBase+32) ->
    // out4 indices [warpBase*8, warpBase*8+256). 8 coalesced STG.128.
    const int warpBase = blockIdx.x * blockDim.x + wrow;
    float4* dst = out4 + (size_t)warpBase * 8;
    #pragma unroll
    for (int j = 0; j < 8; ++j) {
        int idx = j * 32 + lane;
        int p = idx >> 3;            // point within warp
        int k = idx & 7;             // float4 index within point
        if (warpBase + p < N)
            dst[idx] = sm[wrow + p][k];
    }
}

extern "C" void kernel_launch(void* const* d_in, const int* in_sizes, int n_in,
                              void* d_out, int out_size)
{
    const float* positions   = (const float*)d_in[0];   // (N, 3)
    const float* hash_tables = (const float*)d_in[1];   // (L, T, F)
    float4* out = (float4*)d_out;                       // (N, 32 floats)

    int N = in_sizes[0] / 3;

    // Same double-precision libm sequence as the Python reference:
    // GROWTH = exp((log(2048)-log(16))/15); res_l = ceil(16*GROWTH**l).
    ResArr res;
    double growth = exp((log(2048.0) - log(16.0)) / 15.0);
    for (int l = 0; l < L_LEVELS; ++l) {
        res.r[l] = (float)ceil(16.0 * pow(growth, (double)l));
    }

    int threads = 256;
    int blocks = (N + threads - 1) / threads;
    hashgrid_kernel<<<blocks, threads>>>(positions, hash_tables, out, N, res);
}

// round 5
// speedup vs baseline: 2.3250x; 1.4190x over previous
#include <cuda_runtime.h>
#include <cuda_bf16.h>
#include <math.h>
#include <stdint.h>

// MultiResolutionHashGrid: N=1e6, L=16, T=2^19, F=2.
// R4: branchless x-pair merge. x hashes with prime 1 => when floor_x is even
// the two x-corners are table entries {i0, i0^1} = one aligned float4.
// Unpredicated LDG.128 fetches both; a PTX-predicated LDG.64 supplies the
// second corner only in odd-x lanes (no wavefront when predicated off).
// Outputs stored as float4 (two levels per store). No branches, no smem.

#define L_LEVELS 16
#define T_SIZE   524288u          // 2^19
#define T_MASK   (T_SIZE - 1u)
#define P1 2654435761u
#define P2 805459861u

struct ResArr { float r[L_LEVELS]; };

// Predicated non-coherent float2 load: no memory work when pred==0.
__device__ __forceinline__ float2 ldg_pred(const float2* p, uint32_t pred) {
    float2 r;
    asm("{\n\t"
        ".reg .pred p;\n\t"
        "setp.ne.u32 p, %2, 0;\n\t"
        "@p ld.global.nc.v2.f32 {%0, %1}, [%3];\n\t"
        "}"
        : "=f"(r.x), "=f"(r.y) : "r"(pred), "l"(p));
    return r;
}

__global__ __launch_bounds__(256)
void hashgrid_kernel(const float* __restrict__ pos,
                     const float* __restrict__ table,
                     float4* __restrict__ out4,
                     int N, ResArr res)
{
    const int n = blockIdx.x * blockDim.x + threadIdx.x;
    if (n >= N) return;

    const float HI = 1.0f - 1e-6f;
    float px = pos[3 * n + 0];
    float py = pos[3 * n + 1];
    float pz = pos[3 * n + 2];
    // normalized = clip((p + 1) / 2.0, 0, 1-1e-6)   (2+1e-8 == 2.0f in f32)
    float nx = fminf(fmaxf((px + 1.0f) * 0.5f, 0.0f), HI);
    float ny = fminf(fmaxf((py + 1.0f) * 0.5f, 0.0f), HI);
    float nz = fminf(fmaxf((pz + 1.0f) * 0.5f, 0.0f), HI);

    const float2* tbl2 = reinterpret_cast<const float2*>(table);
    float4* myout = out4 + (size_t)n * 8;

    float2 oprev;

    #pragma unroll
    for (int l = 0; l < L_LEVELS; ++l) {
        float rr = res.r[l];
        float sx = nx * rr, sy = ny * rr, sz = nz * rr;
        float fx0 = floorf(sx), fy0 = floorf(sy), fz0 = floorf(sz);
        float fx = sx - fx0, fy = sy - fy0, fz = sz - fz0;

        uint32_t cx = (uint32_t)(int32_t)fx0;
        uint32_t cy = (uint32_t)(int32_t)fy0;
        uint32_t cz = (uint32_t)(int32_t)fz0;

        uint32_t x0 = cx;            // x prime is 1
        uint32_t x1 = cx + 1u;
        uint32_t y0 = cy * P1;
        uint32_t y1 = y0 + P1;
        uint32_t z0 = cz * P2;
        uint32_t z1 = z0 + P2;

        const uint32_t oddx = cx & 1u;       // 1 -> need separate x1 load

        const float2* tl  = tbl2 + (size_t)l * T_SIZE;
        const float4* tl4 = reinterpret_cast<const float4*>(tl);

        float2 f000, f100, f001, f101, f010, f110, f011, f111;

        // For mixed hash m = yh ^ zh:
        //   i0 = (x0 ^ m) & MASK. float4 at i0>>1 holds entries {i0&~1, i0|1}.
        //   even x0: i1 = i0 ^ 1 -> other half of the same float4.
        //   odd  x0: i1 arbitrary -> predicated LDG.64.
        #define LOAD_PAIR(m, a, b)                                             \
        do {                                                                   \
            uint32_t i0  = ((x0) ^ (m)) & T_MASK;                              \
            uint32_t i1  = ((x1) ^ (m)) & T_MASK;                              \
            float4  v  = __ldg(&tl4[i0 >> 1]);                                 \
            float2  w  = ldg_pred(&tl[i1], oddx);                              \
            float2 lo2 = make_float2(v.x, v.y);                                \
            float2 hi2 = make_float2(v.z, v.w);                                \
            bool bit  = (i0 & 1u) != 0u;                                       \
            (a) = bit ? hi2 : lo2;                                             \
            float2 bev = bit ? lo2 : hi2;                                      \
            (b) = oddx ? w : bev;                                              \
        } while (0)

        LOAD_PAIR(y0 ^ z0, f000, f100);
        LOAD_PAIR(y0 ^ z1, f001, f101);
        LOAD_PAIR(y1 ^ z0, f010, f110);
        LOAD_PAIR(y1 ^ z1, f011, f111);
        #undef LOAD_PAIR

        float omz = 1.0f - fz;
        float c00x = f000.x * omz + f001.x * fz;
        float c00y = f000.y * omz + f001.y * fz;
        float c01x = f010.x * omz + f011.x * fz;
        float c01y = f010.y * omz + f011.y * fz;
        float c10x = f100.x * omz + f101.x * fz;
        float c10y = f100.y * omz + f101.y * fz;
        float c11x = f110.x * omz + f111.x * fz;
        float c11y = f110.y * omz + f111.y * fz;

        float omy = 1.0f - fy;
        float c0x = c00x * omy + c01x * fy;
        float c0y = c00y * omy + c01y * fy;
        float c1x = c10x * omy + c11x * fy;
        float c1y = c10y * omy + c11y * fy;

        float omx = 1.0f - fx;
        float2 o;
        o.x = c0x * omx + c1x * fx;
        o.y = c0y * omx + c1y * fx;

        if (l & 1) {
            myout[l >> 1] = make_float4(oprev.x, oprev.y, o.x, o.y);
        } else {
            oprev = o;
        }
    }
}

extern "C" void kernel_launch(void* const* d_in, const int* in_sizes, int n_in,
                              void* d_out, int out_size)
{
    const float* positions   = (const float*)d_in[0];   // (N, 3)
    const float* hash_tables = (const float*)d_in[1];   // (L, T, F)
    float4* out = (float4*)d_out;                       // (N, 32 floats)

    int N = in_sizes[0] / 3;

    // Same double-precision libm sequence as the Python reference:
    // GROWTH = exp((log(2048)-log(16))/15); res_l = ceil(16*GROWTH**l).
    ResArr res;
    double growth = exp((log(2048.0) - log(16.0)) / 15.0);
    for (int l = 0; l < L_LEVELS; ++l) {
        res.r[l] = (float)ceil(16.0 * pow(growth, (double)l));
    }

    int threads = 256;
    int blocks = (N + threads - 1) / threads;
    hashgrid_kernel<<<blocks, threads>>>(positions, hash_tables, out, N, res);
}

// round 6
// speedup vs baseline: 2.4689x; 1.0619x over previous
#include <cuda_runtime.h>
#include <cuda_bf16.h>
#include <math.h>
#include <stdint.h>

// MultiResolutionHashGrid: N=1e6, L=16, T=2^19, F=2.
// R6 = R4 (branchless x-pair merge via LDG.128 + predicated LDG.64)
//    + smem-staged warp-coalesced output (free: kernel is reg-bound at 1 CTA/SM).

#define L_LEVELS 16
#define T_SIZE   524288u          // 2^19
#define T_MASK   (T_SIZE - 1u)
#define P1 2654435761u
#define P2 805459861u

struct ResArr { float r[L_LEVELS]; };

// Predicated non-coherent float2 load: no memory work when pred==0.
__device__ __forceinline__ float2 ldg_pred(const float2* p, uint32_t pred) {
    float2 r;
    asm("{\n\t"
        ".reg .pred p;\n\t"
        "setp.ne.u32 p, %2, 0;\n\t"
        "@p ld.global.nc.v2.f32 {%0, %1}, [%3];\n\t"
        "}"
        : "=f"(r.x), "=f"(r.y) : "r"(pred), "l"(p));
    return r;
}

__global__ __launch_bounds__(256)
void hashgrid_kernel(const float* __restrict__ pos,
                     const float* __restrict__ table,
                     float4* __restrict__ out4,
                     int N, ResArr res)
{
    // 256 threads x (8 data + 1 pad) float4 = 36 KB; pad keeps flush
    // LDS.128 conflict-free. Kernel is register-bound (1 CTA/SM), so this
    // smem costs zero occupancy.
    __shared__ float4 sm[256][9];

    const int t    = threadIdx.x;
    const int lane = t & 31;
    const int wrow = t & ~31;
    const int n    = blockIdx.x * blockDim.x + t;

    if (n < N) {
        const float HI = 1.0f - 1e-6f;
        float px = pos[3 * n + 0];
        float py = pos[3 * n + 1];
        float pz = pos[3 * n + 2];
        // normalized = clip((p + 1) / 2.0, 0, 1-1e-6)   (2+1e-8 == 2.0f in f32)
        float nx = fminf(fmaxf((px + 1.0f) * 0.5f, 0.0f), HI);
        float ny = fminf(fmaxf((py + 1.0f) * 0.5f, 0.0f), HI);
        float nz = fminf(fmaxf((pz + 1.0f) * 0.5f, 0.0f), HI);

        const float2* tbl2 = reinterpret_cast<const float2*>(table);
        float2* mysm = reinterpret_cast<float2*>(&sm[t][0]);

        #pragma unroll
        for (int l = 0; l < L_LEVELS; ++l) {
            float rr = res.r[l];
            float sx = nx * rr, sy = ny * rr, sz = nz * rr;
            float fx0 = floorf(sx), fy0 = floorf(sy), fz0 = floorf(sz);
            float fx = sx - fx0, fy = sy - fy0, fz = sz - fz0;

            uint32_t cx = (uint32_t)(int32_t)fx0;
            uint32_t cy = (uint32_t)(int32_t)fy0;
            uint32_t cz = (uint32_t)(int32_t)fz0;

            uint32_t x0 = cx;            // x prime is 1
            uint32_t x1 = cx + 1u;
            uint32_t y0 = cy * P1;
            uint32_t y1 = y0 + P1;
            uint32_t z0 = cz * P2;
            uint32_t z1 = z0 + P2;

            const uint32_t oddx = cx & 1u;   // 1 -> need separate x1 load

            const float2* tl  = tbl2 + (size_t)l * T_SIZE;
            const float4* tl4 = reinterpret_cast<const float4*>(tl);

            float2 f000, f100, f001, f101, f010, f110, f011, f111;

            // For mixed hash m = yh ^ zh:
            //   i0 = (x0 ^ m) & MASK; float4 at i0>>1 holds {i0&~1, i0|1}.
            //   even x0: i1 = i0 ^ 1 -> other half of the same float4.
            //   odd  x0: i1 arbitrary -> predicated LDG.64.
            #define LOAD_PAIR(m, a, b)                                         \
            do {                                                               \
                uint32_t i0  = ((x0) ^ (m)) & T_MASK;                          \
                uint32_t i1  = ((x1) ^ (m)) & T_MASK;                          \
                float4  v  = __ldg(&tl4[i0 >> 1]);                             \
                float2  w  = ldg_pred(&tl[i1], oddx);                          \
                float2 lo2 = make_float2(v.x, v.y);                            \
                float2 hi2 = make_float2(v.z, v.w);                            \
                bool bit  = (i0 & 1u) != 0u;                                   \
                (a) = bit ? hi2 : lo2;                                         \
                float2 bev = bit ? lo2 : hi2;                                  \
                (b) = oddx ? w : bev;                                          \
            } while (0)

            LOAD_PAIR(y0 ^ z0, f000, f100);
            LOAD_PAIR(y0 ^ z1, f001, f101);
            LOAD_PAIR(y1 ^ z0, f010, f110);
            LOAD_PAIR(y1 ^ z1, f011, f111);
            #undef LOAD_PAIR

            float omz = 1.0f - fz;
            float c00x = f000.x * omz + f001.x * fz;
            float c00y = f000.y * omz + f001.y * fz;
            float c01x = f010.x * omz + f011.x * fz;
            float c01y = f010.y * omz + f011.y * fz;
            float c10x = f100.x * omz + f101.x * fz;
            float c10y = f100.y * omz + f101.y * fz;
            float c11x = f110.x * omz + f111.x * fz;
            float c11y = f110.y * omz + f111.y * fz;

            float omy = 1.0f - fy;
            float c0x = c00x * omy + c01x * fy;
            float c0y = c00y * omy + c01y * fy;
            float c1x = c10x * omy + c11x * fy;
            float c1y = c10y * omy + c11y * fy;

            float omx = 1.0f - fx;
            float2 o;
            o.x = c0x * omx + c1x * fx;
            o.y = c0y * omx + c1y * fx;
            mysm[l] = o;
        }
    }
    __syncwarp();

    // Coalesced flush: warp owns points [warpBase, warpBase+32) ->
    // out4 indices [warpBase*8, warpBase*8+256). 8 coalesced STG.128.
    const int warpBase = blockIdx.x * blockDim.x + wrow;
    float4* dst = out4 + (size_t)warpBase * 8;
    #pragma unroll
    for (int j = 0; j < 8; ++j) {
        int idx = j * 32 + lane;
        int p = idx >> 3;            // point within warp
        int k = idx & 7;             // float4 index within point
        if (warpBase + p < N)
            dst[idx] = sm[wrow + p][k];
    }
}

extern "C" void kernel_launch(void* const* d_in, const int* in_sizes, int n_in,
                              void* d_out, int out_size)
{
    const float* positions   = (const float*)d_in[0];   // (N, 3)
    const float* hash_tables = (const float*)d_in[1];   // (L, T, F)
    float4* out = (float4*)d_out;                       // (N, 32 floats)

    int N = in_sizes[0] / 3;

    // Same double-precision libm sequence as the Python reference:
    // GROWTH = exp((log(2048)-log(16))/15); res_l = ceil(16*GROWTH**l).
    ResArr res;
    double growth = exp((log(2048.0) - log(16.0)) / 15.0);
    for (int l = 0; l < L_LEVELS; ++l) {
        res.r[l] = (float)ceil(16.0 * pow(growth, (double)l));
    }

    int threads = 256;
    int blocks = (N + threads - 1) / threads;
    hashgrid_kernel<<<blocks, threads>>>(positions, hash_tables, out, N, res);
}